// round 16
// baseline (speedup 1.0000x reference)
#include <cuda_runtime.h>
#include <cstdint>
#include <cstddef>

typedef unsigned long long ull;

#define Tlen   512
#define NB     4096
#define NTHR   576          // w0-15: MMA (layer=w>>2, mt=(w&3)>>1, nth=w&1); w16: stager; w17: fc
#define NTICKS (Tlen + 4)

// interleaved column position: logical col k -> storage pos (pairs (k,k+4) adjacent)
#define COLPOS(k) (((k) & ~7) | ((((k) & 3) << 1) | (((k) >> 2) & 1)))

#define BARSYNC(id, cnt) asm volatile("bar.sync %0, %1;" :: "r"(id), "r"(cnt) : "memory")

// smem float offsets
#define WB0_OFF   0                    // [13nt][4kt][2pass][64] = 6656
#define WB123_OFF 6656                 // 3 x [13][7][2][64] = 34944
#define BIAS_OFF  41600                // [4][104] fragment-col order
#define WFC_OFF   42016                // 64, interleaved positions
#define V0_OFF    42080                // [2buf][32row][36] = 2304
#define V123_OFF  44384                // [3layer][2buf][32row][60] = 11520
#define SMEM_FLOATS 55904              // 223616 bytes

__device__ __forceinline__ ull pack2(float lo, float hi) {
    return (ull)__float_as_uint(lo) | ((ull)__float_as_uint(hi) << 32);
}
__device__ __forceinline__ float hsum2(ull v) {
    return __uint_as_float((unsigned)v) + __uint_as_float((unsigned)(v >> 32));
}
__device__ __forceinline__ void fma2(ull& acc, ull a, ull b) {
    asm("fma.rn.f32x2 %0, %1, %2, %0;" : "+l"(acc) : "l"(a), "l"(b));
}
__device__ __forceinline__ float fast_sig(float x) {
    float e, r;
    asm("ex2.approx.ftz.f32 %0, %1;" : "=f"(e) : "f"(x * -1.4426950408889634f));
    asm("rcp.approx.ftz.f32 %0, %1;" : "=f"(r) : "f"(e + 1.0f));
    return r;
}
__device__ __forceinline__ float fast_tanh(float x) {
    return fmaf(2.0f, fast_sig(2.0f * x), -1.0f);
}
__device__ __forceinline__ float tf_hi(float v) {
    return __uint_as_float(__float_as_uint(v) & 0xFFFFE000u);
}
__device__ __forceinline__ void mma8(float& d0, float& d1, float& d2, float& d3,
                                     float a0, float a1, float a2, float a3,
                                     float b0, float b1) {
    asm("mma.sync.aligned.m16n8k8.row.col.f32.tf32.tf32.f32 "
        "{%0,%1,%2,%3},{%4,%5,%6,%7},{%8,%9},{%0,%1,%2,%3};"
        : "+f"(d0), "+f"(d1), "+f"(d2), "+f"(d3)
        : "r"(__float_as_uint(a0)), "r"(__float_as_uint(a1)),
          "r"(__float_as_uint(a2)), "r"(__float_as_uint(a3)),
          "r"(__float_as_uint(b0)), "r"(__float_as_uint(b1)));
}

// staging map: tile nt, local col lc -> (unit, gate). Pair layout for nt<12,
// old 2-unit layout for the special tile nt==12 (covers unit 24).
__device__ __forceinline__ void col_map(int nt, int lc, int& u, int& gidx) {
    if (nt < 12) { u = 4 * (nt >> 1) + (lc >> 1); gidx = ((nt & 1) << 1) | (lc & 1); }
    else         { u = 24 + (lc >> 2);            gidx = lc & 3; }
}

// one layer-tick slice: pairs [PAIR0, PAIR0+NPAIR) (+ special tile if SPEC).
template<int KT, int ROWW, int SELFC, int PAIR0, int NPAIR, int SPEC>
__device__ __forceinline__ void layer_tick(
    const float* __restrict__ vr, float* __restrict__ vself,
    float* __restrict__ vchild, const float* __restrict__ wb,
    const float* __restrict__ biasL, float* __restrict__ cst,
    int lane, int rA)
{
    const int c4 = lane & 3;

    float ah[KT][4], al[KT][4];
#pragma unroll
    for (int kt = 0; kt < KT; ++kt) {
        float2 p0 = *(const float2*)(vr + rA * ROWW + kt * 8 + 2 * c4);
        float2 p1 = *(const float2*)(vr + (rA + 8) * ROWW + kt * 8 + 2 * c4);
        ah[kt][0] = tf_hi(p0.x); al[kt][0] = p0.x - ah[kt][0];
        ah[kt][1] = tf_hi(p1.x); al[kt][1] = p1.x - ah[kt][1];
        ah[kt][2] = tf_hi(p0.y); al[kt][2] = p0.y - ah[kt][2];
        ah[kt][3] = tf_hi(p1.y); al[kt][3] = p1.y - ah[kt][3];
    }

#pragma unroll
    for (int pp = 0; pp < NPAIR; ++pp) {
        const int pa = PAIR0 + pp;
        const int nt0 = 2 * pa, nt1 = nt0 + 1;
        float2 bb0 = *(const float2*)(biasL + nt0 * 8 + 2 * c4);
        float2 bb1 = *(const float2*)(biasL + nt1 * 8 + 2 * c4);
        float eA0 = bb0.x, eA1 = bb0.y, eA2 = bb0.x, eA3 = bb0.y;  // (i,f) hi chain
        float eB0 = 0.f, eB1 = 0.f, eB2 = 0.f, eB3 = 0.f;          // (i,f) corr
        float fA0 = bb1.x, fA1 = bb1.y, fA2 = bb1.x, fA3 = bb1.y;  // (g,o) hi chain
        float fB0 = 0.f, fB1 = 0.f, fB2 = 0.f, fB3 = 0.f;          // (g,o) corr
        const float* wp0 = wb + nt0 * KT * 128;
        const float* wp1 = wb + nt1 * KT * 128;
#pragma unroll
        for (int kt = 0; kt < KT; ++kt) {
            float2 bh0 = *(const float2*)(wp0 + kt * 128 + lane * 2);
            float2 bl0 = *(const float2*)(wp0 + kt * 128 + 64 + lane * 2);
            float2 bh1 = *(const float2*)(wp1 + kt * 128 + lane * 2);
            float2 bl1 = *(const float2*)(wp1 + kt * 128 + 64 + lane * 2);
            mma8(eA0, eA1, eA2, eA3, ah[kt][0], ah[kt][1], ah[kt][2], ah[kt][3], bh0.x, bh0.y);
            mma8(fA0, fA1, fA2, fA3, ah[kt][0], ah[kt][1], ah[kt][2], ah[kt][3], bh1.x, bh1.y);
            mma8(eB0, eB1, eB2, eB3, al[kt][0], al[kt][1], al[kt][2], al[kt][3], bh0.x, bh0.y);
            mma8(fB0, fB1, fB2, fB3, al[kt][0], al[kt][1], al[kt][2], al[kt][3], bh1.x, bh1.y);
            mma8(eB0, eB1, eB2, eB3, ah[kt][0], ah[kt][1], ah[kt][2], ah[kt][3], bl0.x, bl0.y);
            mma8(fB0, fB1, fB2, fB3, ah[kt][0], ah[kt][1], ah[kt][2], ah[kt][3], bl1.x, bl1.y);
        }
        // thread-local full gate set: unit u = 4*pa + c4 (always < 25)
        float i0 = fast_sig(eA0 + eB0), f0 = fast_sig(eA1 + eB1);
        float g0 = fast_tanh(fA0 + fB0), o0 = fast_sig(fA1 + fB1);
        float i1 = fast_sig(eA2 + eB2), f1 = fast_sig(eA3 + eB3);
        float g1 = fast_tanh(fA2 + fB2), o1 = fast_sig(fA3 + fB3);
        float c0 = fmaf(f0, cst[pp * 2 + 0], i0 * g0);
        float c1 = fmaf(f1, cst[pp * 2 + 1], i1 * g1);
        cst[pp * 2 + 0] = c0; cst[pp * 2 + 1] = c1;
        float h0 = o0 * fast_tanh(c0);
        float h1 = o1 * fast_tanh(c1);
        const int u = 4 * pa + c4;
        const int cps = COLPOS(SELFC + u);
        vself[rA * ROWW + cps]       = h0;
        vself[(rA + 8) * ROWW + cps] = h1;
        if (vchild) {
            const int cpc = COLPOS(u);
            vchild[rA * 60 + cpc]       = h0;
            vchild[(rA + 8) * 60 + cpc] = h1;
        }
    }

    if (SPEC) {   // tile 12: unit 24, old 2-thread gate layout + shfl exchange
        float2 bb = *(const float2*)(biasL + 12 * 8 + 2 * c4);
        float eA0 = bb.x, eA1 = bb.y, eA2 = bb.x, eA3 = bb.y;
        float eB0 = 0.f, eB1 = 0.f, eB2 = 0.f, eB3 = 0.f;
        const float* wp = wb + 12 * KT * 128;
#pragma unroll
        for (int kt = 0; kt < KT; ++kt) {
            float2 bh = *(const float2*)(wp + kt * 128 + lane * 2);
            float2 bl = *(const float2*)(wp + kt * 128 + 64 + lane * 2);
            mma8(eA0, eA1, eA2, eA3, ah[kt][0], ah[kt][1], ah[kt][2], ah[kt][3], bh.x, bh.y);
            mma8(eB0, eB1, eB2, eB3, al[kt][0], al[kt][1], al[kt][2], al[kt][3], bh.x, bh.y);
            mma8(eB0, eB1, eB2, eB3, ah[kt][0], ah[kt][1], ah[kt][2], ah[kt][3], bl.x, bl.y);
        }
        const int podd = c4 & 1;
        const float kmul = podd ? 2.f : 1.f, kadd = podd ? -1.f : 0.f;
        float d0 = eA0 + eB0, d1 = eA1 + eB1, d2 = eA2 + eB2, d3 = eA3 + eB3;
        const int u = 24 + (c4 >> 1);
        float a0 = fmaf(kmul, fast_sig(kmul * d0), kadd);
        float a1 = fast_sig(d1);
        float a2 = fmaf(kmul, fast_sig(kmul * d2), kadd);
        float a3 = fast_sig(d3);
        float x0 = __shfl_xor_sync(0xFFFFFFFFu, a0, 1);
        float x1 = __shfl_xor_sync(0xFFFFFFFFu, a1, 1);
        float x2 = __shfl_xor_sync(0xFFFFFFFFu, a2, 1);
        float x3 = __shfl_xor_sync(0xFFFFFFFFu, a3, 1);
        float i0 = podd ? x0 : a0, f0 = podd ? x1 : a1;
        float g0 = podd ? a0 : x0, o0 = podd ? a1 : x1;
        float i1 = podd ? x2 : a2, f1 = podd ? x3 : a3;
        float g1 = podd ? a2 : x2, o1 = podd ? a3 : x3;
        float c0 = fmaf(f0, cst[NPAIR * 2 + 0], i0 * g0);
        float c1 = fmaf(f1, cst[NPAIR * 2 + 1], i1 * g1);
        float h0 = o0 * fast_tanh(c0);
        float h1 = o1 * fast_tanh(c1);
        if (u < 25) {
            cst[NPAIR * 2 + 0] = c0; cst[NPAIR * 2 + 1] = c1;
            if (!podd) {
                const int cps = COLPOS(SELFC + u);
                vself[rA * ROWW + cps]       = h0;
                vself[(rA + 8) * ROWW + cps] = h1;
            } else if (vchild) {
                const int cpc = COLPOS(u);
                vchild[rA * 60 + cpc]       = h0;
                vchild[(rA + 8) * 60 + cpc] = h1;
            }
        }
    }
}

__global__ void __launch_bounds__(NTHR) lstm_kernel(
    const float* __restrict__ x,
    const float* __restrict__ Wih1, const float* __restrict__ Whh1,
    const float* __restrict__ bih1, const float* __restrict__ bhh1,
    const float* __restrict__ Wih2, const float* __restrict__ Whh2,
    const float* __restrict__ bih2, const float* __restrict__ bhh2,
    const float* __restrict__ Wih3, const float* __restrict__ Whh3,
    const float* __restrict__ bih3, const float* __restrict__ bhh3,
    const float* __restrict__ Wih4, const float* __restrict__ Whh4,
    const float* __restrict__ bih4, const float* __restrict__ bhh4,
    const float* __restrict__ Wfc, const float* __restrict__ bfc,
    float* __restrict__ out, int write_states)
{
    extern __shared__ float smem[];
    const int tid = threadIdx.x, lane = tid & 31, wid = tid >> 5;
    const int gb0 = blockIdx.x * 32;
    const float* WihL[4] = {Wih1, Wih2, Wih3, Wih4};
    const float* WhhL[4] = {Whh1, Whh2, Whh3, Whh4};
    const float* bihL[4] = {bih1, bih2, bih3, bih4};
    const float* bhhL[4] = {bhh1, bhh2, bhh3, bhh4};

    // ---- stage B fragments (hi pass 0, lo pass 1), pair-relaid columns ----
    for (int i = tid; i < 6656; i += NTHR) {           // layer 1, KT=4
        int nt = i >> 9, r = i & 511, kt = r >> 7, r2 = r & 127;
        int pass = r2 >> 6, e = r2 & 63, ln = e >> 1, j = e & 1;
        int lc = ln >> 2;
        int k = kt * 8 + (ln & 3) + 4 * j;
        int u, gidx; col_map(nt, lc, u, gidx);
        float w = 0.f;
        if (u < 25) {
            int row = gidx * 25 + u;
            if (k == 0)       w = Wih1[row];
            else if (k <= 25) w = Whh1[row * 25 + k - 1];
        }
        float hi = tf_hi(w);
        smem[WB0_OFF + i] = pass ? (w - hi) : hi;
    }
    for (int i = tid; i < 34944; i += NTHR) {          // layers 2-4, KT=7
        int l = i / 11648, r0 = i - l * 11648;
        int nt = r0 / 896, r = r0 - nt * 896, kt = r >> 7, r2 = r & 127;
        int pass = r2 >> 6, e = r2 & 63, ln = e >> 1, j = e & 1;
        int lc = ln >> 2;
        int k = kt * 8 + (ln & 3) + 4 * j;
        int u, gidx; col_map(nt, lc, u, gidx);
        float w = 0.f;
        if (u < 25) {
            int row = gidx * 25 + u;
            if (k <= 24)                 w = WihL[l + 1][row * 25 + k];
            else if (k >= 28 && k <= 52) w = WhhL[l + 1][row * 25 + k - 28];
        }
        float hi = tf_hi(w);
        smem[WB123_OFF + i] = pass ? (w - hi) : hi;
    }
    for (int i = tid; i < 416; i += NTHR) {            // bias in new col order
        int l = i / 104, c = i - l * 104;
        int u, gidx; col_map(c >> 3, c & 7, u, gidx);
        smem[BIAS_OFF + i] = (u < 25) ? (bihL[l][gidx * 25 + u] + bhhL[l][gidx * 25 + u]) : 0.f;
    }
    for (int i = tid; i < 64; i += NTHR) {             // wfc in interleaved positions
        int grp = i >> 3, idx = i & 7;
        int k = grp * 8 + ((idx & 1) << 2) + (idx >> 1);
        smem[WFC_OFF + i] = (k >= 28 && k < 53) ? Wfc[k - 28] : 0.f;
    }
    for (int i = tid; i < 2304 + 11520; i += NTHR) smem[V0_OFF + i] = 0.f;

    const int layer = wid >> 2, mt = (wid & 3) >> 1, nth = wid & 1;
    const int rA = mt * 16 + (lane >> 2);

    float xreg = 0.f, bfc_reg = 0.f;
    if (wid == 16) {
        smem[V0_OFF + lane * 36] = x[gb0 + lane];      // logical col 0 -> pos 0
        xreg = x[(size_t)NB + gb0 + lane];
    }
    if (wid == 17) bfc_reg = bfc[0];
    __syncthreads();

    float cst[8];
#pragma unroll
    for (int i = 0; i < 8; ++i) cst[i] = 0.f;

    // named-barrier counts: B_l id = l+1; B0,B4 are 5-warp (160), B1-B3 8-warp (256)
    const int bidLo = layer + 1, bidHi = layer + 2;
    const int cntLo = (layer == 0) ? 160 : 256;
    const int cntHi = (layer == 3) ? 160 : 256;

    for (int T = 0; T < NTICKS; ++T) {
        if (wid == 16) {                               // x stager
            smem[V0_OFF + ((T + 1) & 1) * 1152 + lane * 36] = xreg;
            int t2 = (T + 2 < Tlen) ? T + 2 : Tlen - 1;
            xreg = x[(size_t)t2 * NB + gb0 + lane];
            BARSYNC(1, 160);                           // B0 with layer-0 warps
        } else if (wid == 17) {                        // fc: y(T-4)
            if (T >= 4) {
                const ulonglong2* V3 = (const ulonglong2*)(smem + V123_OFF + 2 * 3840
                                       + ((T + 1) & 1) * 1920 + lane * 60);
                const ulonglong2* WF = (const ulonglong2*)(smem + WFC_OFF);
                ull A = pack2(bfc_reg, 0.f), B = 0ull;
#pragma unroll
                for (int ch = 6; ch < 14; ++ch) {      // positions 24..55 cover k 28..52
                    ulonglong2 hv = V3[ch]; ulonglong2 w = WF[ch];
                    fma2(A, w.x, hv.x); fma2(B, w.y, hv.y);
                }
                out[(size_t)(T - 4) * NB + gb0 + lane] = hsum2(A) + hsum2(B);
            }
            BARSYNC(5, 160);                           // B4 with layer-3 warps
        } else {
            if (T >= layer && T - layer < Tlen) {
                const int par = (T + layer) & 1;
                if (layer == 0) {
                    const float* vr = smem + V0_OFF + par * 1152;
                    float* vs = smem + V0_OFF + (par ^ 1) * 1152;
                    float* vc = smem + V123_OFF + par * 1920;
                    if (nth == 0)
                        layer_tick<4, 36, 1, 0, 3, 1>(vr, vs, vc, smem + WB0_OFF,
                                                      smem + BIAS_OFF, cst, lane, rA);
                    else
                        layer_tick<4, 36, 1, 3, 3, 0>(vr, vs, vc, smem + WB0_OFF,
                                                      smem + BIAS_OFF, cst, lane, rA);
                } else {
                    const float* vr = smem + V123_OFF + (layer - 1) * 3840 + par * 1920;
                    float* vs = smem + V123_OFF + (layer - 1) * 3840 + (par ^ 1) * 1920;
                    float* vc = (layer < 3) ? smem + V123_OFF + layer * 3840 + par * 1920
                                            : (float*)0;
                    const float* wb = smem + WB123_OFF + (layer - 1) * 11648;
                    const float* bs = smem + BIAS_OFF + layer * 104;
                    if (nth == 0)
                        layer_tick<7, 60, 28, 0, 3, 1>(vr, vs, vc, wb, bs, cst, lane, rA);
                    else
                        layer_tick<7, 60, 28, 3, 3, 0>(vr, vs, vc, wb, bs, cst, lane, rA);
                }
            }
            // chained pipeline barriers, ascending ids (deadlock-free):
            // B_layer gates this layer's next-tick inputs; B_{layer+1} hands off to child.
            BARSYNC(bidLo, cntLo);
            BARSYNC(bidHi, cntHi);
        }
    }
    __syncthreads();   // quiesce all roles before final-state reads

    // ---- final states ----
    if (write_states && wid < 16) {
        size_t base = (size_t)Tlen * NB;
        const size_t S = (size_t)NB * 25;
        const int c4 = lane & 3;
        const int roww  = (layer == 0) ? 36 : 60;
        const int selfc = (layer == 0) ? 1 : 28;
        const float* vb0 = (layer == 0) ? smem + V0_OFF
                          : smem + V123_OFF + (layer - 1) * 3840;
        const int P0 = nth ? 3 : 0;
#pragma unroll
        for (int pi = 0; pi < 3; ++pi) {
            const int u = 4 * (P0 + pi) + c4;
            const int cps = COLPOS(selfc + u);
#pragma unroll
            for (int r2 = 0; r2 < 2; ++r2) {
                int row = rA + 8 * r2;
                size_t idx = (size_t)(gb0 + row) * 25 + u;
                out[base + (size_t)(2 * layer) * S + idx]     = vb0[row * roww + cps];
                out[base + (size_t)(2 * layer + 1) * S + idx] = cst[pi * 2 + r2];
            }
        }
        if (nth == 0 && c4 == 0) {                    // special tile: unit 24
            const int cps = COLPOS(selfc + 24);
#pragma unroll
            for (int r2 = 0; r2 < 2; ++r2) {
                int row = rA + 8 * r2;
                size_t idx = (size_t)(gb0 + row) * 25 + 24;
                out[base + (size_t)(2 * layer) * S + idx]     = vb0[row * roww + cps];
                out[base + (size_t)(2 * layer + 1) * S + idx] = cst[6 + r2];
            }
        }
    }
}

extern "C" void kernel_launch(void* const* d_in, const int* in_sizes, int n_in,
                              void* d_out, int out_size) {
    (void)n_in; (void)in_sizes;
    const float* a[19];
    for (int i = 0; i < 19; ++i) a[i] = (const float*)d_in[i];
    int smem_bytes = SMEM_FLOATS * (int)sizeof(float);
    static int configured = -1;
    if (configured != smem_bytes) {
        cudaFuncSetAttribute(lstm_kernel,
                             cudaFuncAttributeMaxDynamicSharedMemorySize, smem_bytes);
        configured = smem_bytes;
    }
    int write_states = (out_size >= Tlen * NB + 8 * NB * 25) ? 1 : 0;
    lstm_kernel<<<NB / 32, NTHR, smem_bytes>>>(
        a[0], a[1], a[2], a[3], a[4], a[5], a[6], a[7], a[8], a[9],
        a[10], a[11], a[12], a[13], a[14], a[15], a[16], a[17], a[18],
        (float*)d_out, write_states);
}

// round 17
// speedup vs baseline: 1.1382x; 1.1382x over previous
#include <cuda_runtime.h>
#include <cstdint>
#include <cstddef>

typedef unsigned long long ull;

#define Tlen   512
#define NB     4096
#define NTHR   512          // w0-15: MMA (layer=w>>2, mt=(w&3)>>1, nth=w&1); stager on w13, fc on w15
#define NTICKS (Tlen + 4)

// interleaved column position: logical col k -> storage pos (pairs (k,k+4) adjacent)
#define COLPOS(k) (((k) & ~7) | ((((k) & 3) << 1) | (((k) >> 2) & 1)))

// smem float offsets
#define WB0_OFF   0                    // [13nt][4kt][32 lane][4: bh.x bh.y bl.x bl.y] = 6656
#define WB123_OFF 6656                 // 3 x [13][7][32][4] = 34944
#define BIAS_OFF  41600                // [4][104] fragment-col order
#define WFC_OFF   42016                // 64, interleaved positions
#define V0_OFF    42080                // [2buf][32row][36] = 2304
#define V123_OFF  44384                // [3layer][2buf][32row][60] = 11520
#define SMEM_FLOATS 55904              // 223616 bytes

__device__ __forceinline__ ull pack2(float lo, float hi) {
    return (ull)__float_as_uint(lo) | ((ull)__float_as_uint(hi) << 32);
}
__device__ __forceinline__ float hsum2(ull v) {
    return __uint_as_float((unsigned)v) + __uint_as_float((unsigned)(v >> 32));
}
__device__ __forceinline__ void fma2(ull& acc, ull a, ull b) {
    asm("fma.rn.f32x2 %0, %1, %2, %0;" : "+l"(acc) : "l"(a), "l"(b));
}
__device__ __forceinline__ float fast_sig(float x) {
    float e, r;
    asm("ex2.approx.ftz.f32 %0, %1;" : "=f"(e) : "f"(x * -1.4426950408889634f));
    asm("rcp.approx.ftz.f32 %0, %1;" : "=f"(r) : "f"(e + 1.0f));
    return r;
}
__device__ __forceinline__ float fast_tanh(float x) {
    return fmaf(2.0f, fast_sig(2.0f * x), -1.0f);
}
__device__ __forceinline__ float tf_hi(float v) {
    return __uint_as_float(__float_as_uint(v) & 0xFFFFE000u);
}
__device__ __forceinline__ void mma8(float& d0, float& d1, float& d2, float& d3,
                                     float a0, float a1, float a2, float a3,
                                     float b0, float b1) {
    asm("mma.sync.aligned.m16n8k8.row.col.f32.tf32.tf32.f32 "
        "{%0,%1,%2,%3},{%4,%5,%6,%7},{%8,%9},{%0,%1,%2,%3};"
        : "+f"(d0), "+f"(d1), "+f"(d2), "+f"(d3)
        : "r"(__float_as_uint(a0)), "r"(__float_as_uint(a1)),
          "r"(__float_as_uint(a2)), "r"(__float_as_uint(a3)),
          "r"(__float_as_uint(b0)), "r"(__float_as_uint(b1)));
}

// staging map: tile nt, local col lc -> (unit, gate). Pair layout for nt<12,
// old 2-unit layout for the special tile nt==12 (covers unit 24).
__device__ __forceinline__ void col_map(int nt, int lc, int& u, int& gidx) {
    if (nt < 12) { u = 4 * (nt >> 1) + (lc >> 1); gidx = ((nt & 1) << 1) | (lc & 1); }
    else         { u = 24 + (lc >> 2);            gidx = lc & 3; }
}

// one layer-tick slice: pairs [PAIR0, PAIR0+NPAIR) (+ special tile if SPEC).
template<int KT, int ROWW, int SELFC, int PAIR0, int NPAIR, int SPEC>
__device__ __forceinline__ void layer_tick(
    const float* __restrict__ vr, float* __restrict__ vself,
    float* __restrict__ vchild, const float* __restrict__ wb,
    const float* __restrict__ biasL, float* __restrict__ cst,
    int lane, int rA)
{
    const int c4 = lane & 3;

    float ah[KT][4], al[KT][4];
#pragma unroll
    for (int kt = 0; kt < KT; ++kt) {
        float2 p0 = *(const float2*)(vr + rA * ROWW + kt * 8 + 2 * c4);
        float2 p1 = *(const float2*)(vr + (rA + 8) * ROWW + kt * 8 + 2 * c4);
        ah[kt][0] = tf_hi(p0.x); al[kt][0] = p0.x - ah[kt][0];
        ah[kt][1] = tf_hi(p1.x); al[kt][1] = p1.x - ah[kt][1];
        ah[kt][2] = tf_hi(p0.y); al[kt][2] = p0.y - ah[kt][2];
        ah[kt][3] = tf_hi(p1.y); al[kt][3] = p1.y - ah[kt][3];
    }

#pragma unroll
    for (int pp = 0; pp < NPAIR; ++pp) {
        const int pa = PAIR0 + pp;
        const int nt0 = 2 * pa, nt1 = nt0 + 1;
        float2 bb0 = *(const float2*)(biasL + nt0 * 8 + 2 * c4);
        float2 bb1 = *(const float2*)(biasL + nt1 * 8 + 2 * c4);
        float eA0 = bb0.x, eA1 = bb0.y, eA2 = bb0.x, eA3 = bb0.y;  // (i,f) hi chain
        float eB0 = 0.f, eB1 = 0.f, eB2 = 0.f, eB3 = 0.f;          // (i,f) corr
        float fA0 = bb1.x, fA1 = bb1.y, fA2 = bb1.x, fA3 = bb1.y;  // (g,o) hi chain
        float fB0 = 0.f, fB1 = 0.f, fB2 = 0.f, fB3 = 0.f;          // (g,o) corr
        const float* wp0 = wb + nt0 * KT * 128;
        const float* wp1 = wb + nt1 * KT * 128;
#pragma unroll
        for (int kt = 0; kt < KT; ++kt) {
            float4 w0 = *(const float4*)(wp0 + kt * 128 + lane * 4);  // bh.xy, bl.xy
            float4 w1 = *(const float4*)(wp1 + kt * 128 + lane * 4);
            mma8(eA0, eA1, eA2, eA3, ah[kt][0], ah[kt][1], ah[kt][2], ah[kt][3], w0.x, w0.y);
            mma8(fA0, fA1, fA2, fA3, ah[kt][0], ah[kt][1], ah[kt][2], ah[kt][3], w1.x, w1.y);
            mma8(eB0, eB1, eB2, eB3, al[kt][0], al[kt][1], al[kt][2], al[kt][3], w0.x, w0.y);
            mma8(fB0, fB1, fB2, fB3, al[kt][0], al[kt][1], al[kt][2], al[kt][3], w1.x, w1.y);
            mma8(eB0, eB1, eB2, eB3, ah[kt][0], ah[kt][1], ah[kt][2], ah[kt][3], w0.z, w0.w);
            mma8(fB0, fB1, fB2, fB3, ah[kt][0], ah[kt][1], ah[kt][2], ah[kt][3], w1.z, w1.w);
        }
        // thread-local full gate set: unit u = 4*pa + c4 (always < 25)
        float i0 = fast_sig(eA0 + eB0), f0 = fast_sig(eA1 + eB1);
        float g0 = fast_tanh(fA0 + fB0), o0 = fast_sig(fA1 + fB1);
        float i1 = fast_sig(eA2 + eB2), f1 = fast_sig(eA3 + eB3);
        float g1 = fast_tanh(fA2 + fB2), o1 = fast_sig(fA3 + fB3);
        float c0 = fmaf(f0, cst[pp * 2 + 0], i0 * g0);
        float c1 = fmaf(f1, cst[pp * 2 + 1], i1 * g1);
        cst[pp * 2 + 0] = c0; cst[pp * 2 + 1] = c1;
        float h0 = o0 * fast_tanh(c0);
        float h1 = o1 * fast_tanh(c1);
        const int u = 4 * pa + c4;
        const int cps = COLPOS(SELFC + u);
        vself[rA * ROWW + cps]       = h0;
        vself[(rA + 8) * ROWW + cps] = h1;
        if (vchild) {
            const int cpc = COLPOS(u);
            vchild[rA * 60 + cpc]       = h0;
            vchild[(rA + 8) * 60 + cpc] = h1;
        }
    }

    if (SPEC) {   // tile 12: unit 24, old 2-thread gate layout + shfl exchange
        float2 bb = *(const float2*)(biasL + 12 * 8 + 2 * c4);
        float eA0 = bb.x, eA1 = bb.y, eA2 = bb.x, eA3 = bb.y;
        float eB0 = 0.f, eB1 = 0.f, eB2 = 0.f, eB3 = 0.f;
        const float* wp = wb + 12 * KT * 128;
#pragma unroll
        for (int kt = 0; kt < KT; ++kt) {
            float4 w = *(const float4*)(wp + kt * 128 + lane * 4);
            mma8(eA0, eA1, eA2, eA3, ah[kt][0], ah[kt][1], ah[kt][2], ah[kt][3], w.x, w.y);
            mma8(eB0, eB1, eB2, eB3, al[kt][0], al[kt][1], al[kt][2], al[kt][3], w.x, w.y);
            mma8(eB0, eB1, eB2, eB3, ah[kt][0], ah[kt][1], ah[kt][2], ah[kt][3], w.z, w.w);
        }
        const int podd = c4 & 1;
        const float kmul = podd ? 2.f : 1.f, kadd = podd ? -1.f : 0.f;
        float d0 = eA0 + eB0, d1 = eA1 + eB1, d2 = eA2 + eB2, d3 = eA3 + eB3;
        const int u = 24 + (c4 >> 1);
        float a0 = fmaf(kmul, fast_sig(kmul * d0), kadd);
        float a1 = fast_sig(d1);
        float a2 = fmaf(kmul, fast_sig(kmul * d2), kadd);
        float a3 = fast_sig(d3);
        float x0 = __shfl_xor_sync(0xFFFFFFFFu, a0, 1);
        float x1 = __shfl_xor_sync(0xFFFFFFFFu, a1, 1);
        float x2 = __shfl_xor_sync(0xFFFFFFFFu, a2, 1);
        float x3 = __shfl_xor_sync(0xFFFFFFFFu, a3, 1);
        float i0 = podd ? x0 : a0, f0 = podd ? x1 : a1;
        float g0 = podd ? a0 : x0, o0 = podd ? a1 : x1;
        float i1 = podd ? x2 : a2, f1 = podd ? x3 : a3;
        float g1 = podd ? a2 : x2, o1 = podd ? a3 : x3;
        float c0 = fmaf(f0, cst[NPAIR * 2 + 0], i0 * g0);
        float c1 = fmaf(f1, cst[NPAIR * 2 + 1], i1 * g1);
        float h0 = o0 * fast_tanh(c0);
        float h1 = o1 * fast_tanh(c1);
        if (u < 25) {
            cst[NPAIR * 2 + 0] = c0; cst[NPAIR * 2 + 1] = c1;
            if (!podd) {
                const int cps = COLPOS(SELFC + u);
                vself[rA * ROWW + cps]       = h0;
                vself[(rA + 8) * ROWW + cps] = h1;
            } else if (vchild) {
                const int cpc = COLPOS(u);
                vchild[rA * 60 + cpc]       = h0;
                vchild[(rA + 8) * 60 + cpc] = h1;
            }
        }
    }
}

__global__ void __launch_bounds__(NTHR) lstm_kernel(
    const float* __restrict__ x,
    const float* __restrict__ Wih1, const float* __restrict__ Whh1,
    const float* __restrict__ bih1, const float* __restrict__ bhh1,
    const float* __restrict__ Wih2, const float* __restrict__ Whh2,
    const float* __restrict__ bih2, const float* __restrict__ bhh2,
    const float* __restrict__ Wih3, const float* __restrict__ Whh3,
    const float* __restrict__ bih3, const float* __restrict__ bhh3,
    const float* __restrict__ Wih4, const float* __restrict__ Whh4,
    const float* __restrict__ bih4, const float* __restrict__ bhh4,
    const float* __restrict__ Wfc, const float* __restrict__ bfc,
    float* __restrict__ out, int write_states)
{
    extern __shared__ float smem[];
    const int tid = threadIdx.x, lane = tid & 31, wid = tid >> 5;
    const int gb0 = blockIdx.x * 32;
    const float* WihL[4] = {Wih1, Wih2, Wih3, Wih4};
    const float* WhhL[4] = {Whh1, Whh2, Whh3, Whh4};
    const float* bihL[4] = {bih1, bih2, bih3, bih4};
    const float* bhhL[4] = {bhh1, bhh2, bhh3, bhh4};

    // ---- stage B fragments, interleaved per-lane [bh.x bh.y bl.x bl.y] ----
    for (int i = tid; i < 6656; i += NTHR) {           // layer 1, KT=4
        int nt = i >> 9, r = i & 511, kt = r >> 7, r2 = r & 127;
        int ln = r2 >> 2, pass = (r2 >> 1) & 1, j = r2 & 1;
        int lc = ln >> 2;
        int k = kt * 8 + (ln & 3) + 4 * j;
        int u, gidx; col_map(nt, lc, u, gidx);
        float w = 0.f;
        if (u < 25) {
            int row = gidx * 25 + u;
            if (k == 0)       w = Wih1[row];
            else if (k <= 25) w = Whh1[row * 25 + k - 1];
        }
        float hi = tf_hi(w);
        smem[WB0_OFF + i] = pass ? (w - hi) : hi;
    }
    for (int i = tid; i < 34944; i += NTHR) {          // layers 2-4, KT=7
        int l = i / 11648, r0 = i - l * 11648;
        int nt = r0 / 896, r = r0 - nt * 896, kt = r >> 7, r2 = r & 127;
        int ln = r2 >> 2, pass = (r2 >> 1) & 1, j = r2 & 1;
        int lc = ln >> 2;
        int k = kt * 8 + (ln & 3) + 4 * j;
        int u, gidx; col_map(nt, lc, u, gidx);
        float w = 0.f;
        if (u < 25) {
            int row = gidx * 25 + u;
            if (k <= 24)                 w = WihL[l + 1][row * 25 + k];
            else if (k >= 28 && k <= 52) w = WhhL[l + 1][row * 25 + k - 28];
        }
        float hi = tf_hi(w);
        smem[WB123_OFF + i] = pass ? (w - hi) : hi;
    }
    for (int i = tid; i < 416; i += NTHR) {            // bias in fragment-col order
        int l = i / 104, c = i - l * 104;
        int u, gidx; col_map(c >> 3, c & 7, u, gidx);
        smem[BIAS_OFF + i] = (u < 25) ? (bihL[l][gidx * 25 + u] + bhhL[l][gidx * 25 + u]) : 0.f;
    }
    for (int i = tid; i < 64; i += NTHR) {             // wfc in interleaved positions
        int grp = i >> 3, idx = i & 7;
        int k = grp * 8 + ((idx & 1) << 2) + (idx >> 1);
        smem[WFC_OFF + i] = (k >= 28 && k < 53) ? Wfc[k - 28] : 0.f;
    }
    for (int i = tid; i < 2304 + 11520; i += NTHR) smem[V0_OFF + i] = 0.f;

    const int layer = wid >> 2, mt = (wid & 3) >> 1, nth = wid & 1;
    const int rA = mt * 16 + (lane >> 2);

    float xreg = 0.f, bfc_reg = 0.f;
    if (wid == 13) {                                   // stager role (also layer-3 MMA)
        smem[V0_OFF + lane * 36] = x[gb0 + lane];      // x(0) -> buf 0, logical col 0
        xreg = x[(size_t)NB + gb0 + lane];
    }
    if (wid == 15) bfc_reg = bfc[0];                   // fc role (also layer-3 MMA)
    __syncthreads();

    float cst[8];
#pragma unroll
    for (int i = 0; i < 8; ++i) cst[i] = 0.f;

    for (int T = 0; T < NTICKS; ++T) {
        if (wid == 13) {                               // x stager: stage x(T+1)
            smem[V0_OFF + ((T + 1) & 1) * 1152 + lane * 36] = xreg;
            int t2 = (T + 2 < Tlen) ? T + 2 : Tlen - 1;
            xreg = x[(size_t)t2 * NB + gb0 + lane];
        }
        if (wid == 15 && T >= 4) {                     // fc: y(T-4)
            const ulonglong2* V3 = (const ulonglong2*)(smem + V123_OFF + 2 * 3840
                                   + ((T + 1) & 1) * 1920 + lane * 60);
            const ulonglong2* WF = (const ulonglong2*)(smem + WFC_OFF);
            ull A = pack2(bfc_reg, 0.f), B = 0ull;
#pragma unroll
            for (int ch = 6; ch < 14; ++ch) {          // positions 24..55 cover k 28..52
                ulonglong2 hv = V3[ch]; ulonglong2 w = WF[ch];
                fma2(A, w.x, hv.x); fma2(B, w.y, hv.y);
            }
            out[(size_t)(T - 4) * NB + gb0 + lane] = hsum2(A) + hsum2(B);
        }
        if (T >= layer && T - layer < Tlen) {
            const int par = (T + layer) & 1;
            if (layer == 0) {
                const float* vr = smem + V0_OFF + par * 1152;
                float* vs = smem + V0_OFF + (par ^ 1) * 1152;
                float* vc = smem + V123_OFF + par * 1920;
                if (nth == 0)
                    layer_tick<4, 36, 1, 0, 3, 1>(vr, vs, vc, smem + WB0_OFF,
                                                  smem + BIAS_OFF, cst, lane, rA);
                else
                    layer_tick<4, 36, 1, 3, 3, 0>(vr, vs, vc, smem + WB0_OFF,
                                                  smem + BIAS_OFF, cst, lane, rA);
            } else {
                const float* vr = smem + V123_OFF + (layer - 1) * 3840 + par * 1920;
                float* vs = smem + V123_OFF + (layer - 1) * 3840 + (par ^ 1) * 1920;
                float* vc = (layer < 3) ? smem + V123_OFF + layer * 3840 + par * 1920
                                        : (float*)0;
                const float* wb = smem + WB123_OFF + (layer - 1) * 11648;
                const float* bs = smem + BIAS_OFF + layer * 104;
                if (nth == 0)
                    layer_tick<7, 60, 28, 0, 3, 1>(vr, vs, vc, wb, bs, cst, lane, rA);
                else
                    layer_tick<7, 60, 28, 3, 3, 0>(vr, vs, vc, wb, bs, cst, lane, rA);
            }
        }
        __syncthreads();
    }

    // ---- final states ----
    if (write_states) {
        size_t base = (size_t)Tlen * NB;
        const size_t S = (size_t)NB * 25;
        const int c4 = lane & 3;
        const int roww  = (layer == 0) ? 36 : 60;
        const int selfc = (layer == 0) ? 1 : 28;
        const float* vb0 = (layer == 0) ? smem + V0_OFF
                          : smem + V123_OFF + (layer - 1) * 3840;
        const int P0 = nth ? 3 : 0;
#pragma unroll
        for (int pi = 0; pi < 3; ++pi) {
            const int u = 4 * (P0 + pi) + c4;
            const int cps = COLPOS(selfc + u);
#pragma unroll
            for (int r2 = 0; r2 < 2; ++r2) {
                int row = rA + 8 * r2;
                size_t idx = (size_t)(gb0 + row) * 25 + u;
                out[base + (size_t)(2 * layer) * S + idx]     = vb0[row * roww + cps];
                out[base + (size_t)(2 * layer + 1) * S + idx] = cst[pi * 2 + r2];
            }
        }
        if (nth == 0 && c4 == 0) {                    // special tile: unit 24
            const int cps = COLPOS(selfc + 24);
#pragma unroll
            for (int r2 = 0; r2 < 2; ++r2) {
                int row = rA + 8 * r2;
                size_t idx = (size_t)(gb0 + row) * 25 + 24;
                out[base + (size_t)(2 * layer) * S + idx]     = vb0[row * roww + cps];
                out[base + (size_t)(2 * layer + 1) * S + idx] = cst[6 + r2];
            }
        }
    }
}

extern "C" void kernel_launch(void* const* d_in, const int* in_sizes, int n_in,
                              void* d_out, int out_size) {
    (void)n_in; (void)in_sizes;
    const float* a[19];
    for (int i = 0; i < 19; ++i) a[i] = (const float*)d_in[i];
    int smem_bytes = SMEM_FLOATS * (int)sizeof(float);
    static int configured = -1;
    if (configured != smem_bytes) {
        cudaFuncSetAttribute(lstm_kernel,
                             cudaFuncAttributeMaxDynamicSharedMemorySize, smem_bytes);
        configured = smem_bytes;
    }
    int write_states = (out_size >= Tlen * NB + 8 * NB * 25) ? 1 : 0;
    lstm_kernel<<<NB / 32, NTHR, smem_bytes>>>(
        a[0], a[1], a[2], a[3], a[4], a[5], a[6], a[7], a[8], a[9],
        a[10], a[11], a[12], a[13], a[14], a[15], a[16], a[17], a[18],
        (float*)d_out, write_states);
}